// round 8
// baseline (speedup 1.0000x reference)
#include <cuda_runtime.h>
#include <math.h>
#include <stdint.h>

#define BB   128
#define TL   2048
#define HH   200
#define NT   16        // t-tiles per batch row
#define NPAD 208       // padded h/n
#define SA53 53        // A/B smem row stride in words

// ---------------- device scratch ----------------
__device__ float d_qp[BB * NPAD];              // q@Wa.T + ba + bua (pad 0)
__device__ float d_Vap[NPAD];                  // Va padded
__device__ float d_sB[NPAD];                   // per-n Ua scale (0 for n>=200)
__device__ __align__(16) int d_B8[NPAD * SA53];// Ua int8 packed words, stride 53
__device__ float d_mloc[BB * NT];
__device__ float d_zloc[BB * NT];
__device__ float d_ctxp[BB * NT * HH];

// ---------------- helpers ----------------
__device__ __forceinline__ float tanha(float x) {
    float y; asm("tanh.approx.f32 %0, %1;" : "=f"(y) : "f"(x)); return y;
}
__device__ __forceinline__ float sigf(float x) { return 1.0f / (1.0f + __expf(-x)); }
__device__ __forceinline__ uint32_t smem_u32(const void* p) {
    uint32_t a;
    asm("{ .reg .u64 t; cvta.to.shared.u64 t, %1; cvt.u32.u64 %0, t; }" : "=r"(a) : "l"(p));
    return a;
}
__device__ __forceinline__ void cp16(uint32_t dst, const void* src) {
    asm volatile("cp.async.ca.shared.global [%0], [%1], 16;" :: "r"(dst), "l"(src) : "memory");
}
__device__ __forceinline__ int q8(float x, float inv) {
    int v = __float2int_rn(x * inv);
    v = v > 127 ? 127 : v;
    v = v < -127 ? -127 : v;
    return v & 0xff;
}

// SMEM layout (bytes)
#define SM_SA  0        // 128 f
#define SM_SB  512      // 208 f
#define SM_QP  1344     // 208 f
#define SM_VA  2176     // 208 f
#define SM_W   3008     // 128 f  (scores -> weights, in place)
#define SM_WA  3520     // 128 f
#define SM_RED 4032     // 256 f
#define SM_A   5120     // 128*53 words = 27136 B
#define SM_B   32256    // 208*53 words = 44096 B
#define SMEM_SZ 76352

extern __shared__ char sm_dyn[];

// ---------------- 1) setup: qp, Va, B8+sB ----------------
__global__ void setup_kernel(const float* __restrict__ h0,
                             const float* __restrict__ Wa,
                             const float* __restrict__ ba,
                             const float* __restrict__ Ua,
                             const float* __restrict__ bua,
                             const float* __restrict__ Va) {
    int blk = blockIdx.x;
    int tid = threadIdx.x;
    int lane = tid & 31, wid = tid >> 5;
    if (blk < BB) {
        __shared__ float q[HH];
        for (int k = tid; k < HH; k += 256) q[k] = h0[blk * HH + k];
        __syncthreads();
        for (int h = wid; h < NPAD; h += 8) {
            if (h < HH) {
                float acc = 0.f;
                const float* w = Wa + h * HH;
                for (int k = lane; k < HH; k += 32) acc += w[k] * q[k];
                #pragma unroll
                for (int o = 16; o; o >>= 1) acc += __shfl_xor_sync(0xffffffffu, acc, o);
                if (lane == 0) d_qp[blk * NPAD + h] = acc + ba[h] + bua[h];
            } else if (lane == 0) d_qp[blk * NPAD + h] = 0.f;
        }
    } else {
        // B8 image + sB + Va
        if (tid < NPAD) {
            int n = tid;
            if (n < HH) {
                const float* row = Ua + n * HH;
                float mx = 0.f;
                for (int k = 0; k < HH; k++) mx = fmaxf(mx, fabsf(row[k]));
                float inv = (mx > 0.f) ? 127.f / mx : 0.f;
                d_sB[n] = mx * (1.f / 127.f);
                for (int kq = 0; kq < SA53; kq++) {
                    int wv = 0;
                    #pragma unroll
                    for (int j = 0; j < 4; j++) {
                        int k = kq * 4 + j;
                        int b = (k < HH) ? q8(row[k], inv) : 0;
                        wv |= b << (8 * j);
                    }
                    d_B8[n * SA53 + kq] = wv;
                }
            } else {
                d_sB[n] = 0.f;
                for (int kq = 0; kq < SA53; kq++) d_B8[n * SA53 + kq] = 0;
            }
            d_Vap[n] = (n < HH) ? Va[n] : 0.f;
        }
    }
}

// ---------------- GEMM pass helper ----------------
template <int NN>
__device__ __forceinline__ void gemm_pass(const int* __restrict__ ap,
                                          const int* __restrict__ bp,
                                          const float* __restrict__ sAs,
                                          const float* __restrict__ sBs,
                                          const float* __restrict__ qps,
                                          const float* __restrict__ Vas,
                                          int m0, int nbase, float* score) {
    int acc0[NN], acc1[NN], acc2[NN], acc3[NN];
    #pragma unroll
    for (int nn = 0; nn < NN; nn++) { acc0[nn] = 0; acc1[nn] = 0; acc2[nn] = 0; acc3[nn] = 0; }
    #pragma unroll 4
    for (int kq = 0; kq < 52; kq++) {
        int a0 = ap[kq];
        int a1 = ap[SA53 + kq];
        int a2 = ap[2 * SA53 + kq];
        int a3 = ap[3 * SA53 + kq];
        #pragma unroll
        for (int nn = 0; nn < NN; nn++) {
            int bv = bp[nn * 8 * SA53 + kq];
            acc0[nn] = __dp4a(a0, bv, acc0[nn]);
            acc1[nn] = __dp4a(a1, bv, acc1[nn]);
            acc2[nn] = __dp4a(a2, bv, acc2[nn]);
            acc3[nn] = __dp4a(a3, bv, acc3[nn]);
        }
    }
    float sa0 = sAs[m0], sa1 = sAs[m0 + 1], sa2 = sAs[m0 + 2], sa3 = sAs[m0 + 3];
    #pragma unroll
    for (int nn = 0; nn < NN; nn++) {
        int n = nbase + nn * 8;
        float sbn = sBs[n], qn = qps[n], van = Vas[n];
        score[0] += van * tanha(qn + sa0 * sbn * (float)acc0[nn]);
        score[1] += van * tanha(qn + sa1 * sbn * (float)acc1[nn]);
        score[2] += van * tanha(qn + sa2 * sbn * (float)acc2[nn]);
        score[3] += van * tanha(qn + sa3 * sbn * (float)acc3[nn]);
    }
}

// ---------------- 2) fused scores + softmax + partial ctx ----------------
__global__ void __launch_bounds__(256, 2)
scores_kernel(const float* __restrict__ enc) {
    char* smem = sm_dyn;
    uint32_t sb = smem_u32(smem);
    int tid  = threadIdx.x;
    int lane = tid & 31;
    int wid  = tid >> 5;
    int b    = blockIdx.y;
    int tile = blockIdx.x;

    float* sAs = (float*)(smem + SM_SA);
    float* sBs = (float*)(smem + SM_SB);
    float* qps = (float*)(smem + SM_QP);
    float* Vas = (float*)(smem + SM_VA);
    float* ws  = (float*)(smem + SM_W);
    float* was = (float*)(smem + SM_WA);
    float* red = (float*)(smem + SM_RED);
    int* A32s  = (int*)(smem + SM_A);
    int* B32s  = (int*)(smem + SM_B);

    // B image one-shot copy (2756 x 16B)
    for (int i = tid; i < 2756; i += 256)
        cp16(sb + SM_B + i * 16, (const char*)d_B8 + i * 16);
    asm volatile("cp.async.commit_group;" ::: "memory");

    if (tid < NPAD) {
        sBs[tid] = d_sB[tid];
        qps[tid] = d_qp[b * NPAD + tid];
        Vas[tid] = d_Vap[tid];
    }

    // ---- A tile: rowmax pass then quantize pass ----
    int r = tid >> 1, half = tid & 1;
    const float* rp = enc + ((long)(b * TL + tile * 128 + r)) * HH + half * 100;
    float mx = 0.f;
    #pragma unroll 5
    for (int j = 0; j < 25; j++) {
        float4 v = *(const float4*)(rp + j * 4);
        mx = fmaxf(mx, fmaxf(fmaxf(fabsf(v.x), fabsf(v.y)), fmaxf(fabsf(v.z), fabsf(v.w))));
    }
    mx = fmaxf(mx, __shfl_xor_sync(0xffffffffu, mx, 1));
    float inv = (mx > 0.f) ? 127.f / mx : 0.f;
    if (half == 0) sAs[r] = mx * (1.f / 127.f);
    #pragma unroll 5
    for (int j = 0; j < 25; j++) {
        float4 v = *(const float4*)(rp + j * 4);
        int wv = q8(v.x, inv) | (q8(v.y, inv) << 8) | (q8(v.z, inv) << 16) | (q8(v.w, inv) << 24);
        A32s[r * SA53 + half * 25 + j] = wv;
    }
    if (half) { A32s[r * SA53 + 50] = 0; A32s[r * SA53 + 51] = 0; }

    asm volatile("cp.async.wait_group 0;" ::: "memory");
    __syncthreads();

    // ---- dp4a GEMM: thread = 4 m x 8 n, n-passes ----
    int mg = (wid << 2) + (lane >> 3);   // 0..31
    int m0 = mg << 2;
    int ng = lane & 7;
    float score[4] = {0.f, 0.f, 0.f, 0.f};
    const int* ap = A32s + m0 * SA53;

    gemm_pass<8>(ap, B32s + (0 + ng) * SA53,   sAs, sBs, qps, Vas, m0, 0 + ng,   score);
    gemm_pass<8>(ap, B32s + (64 + ng) * SA53,  sAs, sBs, qps, Vas, m0, 64 + ng,  score);
    gemm_pass<8>(ap, B32s + (128 + ng) * SA53, sAs, sBs, qps, Vas, m0, 128 + ng, score);
    gemm_pass<2>(ap, B32s + (192 + ng) * SA53, sAs, sBs, qps, Vas, m0, 192 + ng, score);

    #pragma unroll
    for (int j = 0; j < 4; j++) {
        score[j] += __shfl_xor_sync(0xffffffffu, score[j], 1);
        score[j] += __shfl_xor_sync(0xffffffffu, score[j], 2);
        score[j] += __shfl_xor_sync(0xffffffffu, score[j], 4);
    }
    if (ng == 0) {
        ws[m0]     = score[0];
        ws[m0 + 1] = score[1];
        ws[m0 + 2] = score[2];
        ws[m0 + 3] = score[3];
    }
    __syncthreads();

    // ---- tile-local softmax ----
    float sv = (tid < 128) ? ws[tid] : -1e30f;
    red[tid] = sv;
    __syncthreads();
    for (int s = 128; s; s >>= 1) {
        if (tid < s) red[tid] = fmaxf(red[tid], red[tid + s]);
        __syncthreads();
    }
    float mloc = red[0];
    __syncthreads();
    float wv = (tid < 128) ? __expf(sv - mloc) : 0.f;
    red[tid] = wv;
    __syncthreads();
    for (int s = 128; s; s >>= 1) {
        if (tid < s) red[tid] += red[tid + s];
        __syncthreads();
    }
    float zloc = red[0];
    if (tid < 128) { ws[tid] = wv; was[tid] = wv * sAs[tid]; }
    __syncthreads();

    // ---- partial context from int8 A ----
    if (tid < HH) {
        int widx = tid >> 2;
        int sel = 1 << ((tid & 3) * 8);
        float s = 0.f;
        #pragma unroll 4
        for (int t = 0; t < 128; t++)
            s += was[t] * (float)__dp4a(A32s[t * SA53 + widx], sel, 0);
        d_ctxp[((long)b * NT + tile) * HH + tid] = s;
    }
    if (tid == 0) {
        d_mloc[b * NT + tile] = mloc;
        d_zloc[b * NT + tile] = zloc;
    }
}

// ---------------- 3) decoder: combine + 5 LSTM+MLP steps, 4 b per block ----------------
__global__ void __launch_bounds__(256) decoder_kernel(
        const float* __restrict__ x,
        const float* __restrict__ h0,
        const float* __restrict__ c0,
        const float* __restrict__ W_ih,
        const float* __restrict__ W_hh,
        const float* __restrict__ b_ih,
        const float* __restrict__ b_hh,
        const float* __restrict__ W1, const float* __restrict__ b1,
        const float* __restrict__ W2, const float* __restrict__ b2,
        const float* __restrict__ W3, const float* __restrict__ b3,
        float* __restrict__ out) {
    __shared__ float ctx4[4][HH];
    __shared__ float h04[4][HH];
    __shared__ float gb4[4][800];
    __shared__ float coef[NT];
    __shared__ float zinv_s;
    __shared__ float r[HH];
    __shared__ float s1[100];
    __shared__ float s2[64];
    __shared__ float xb;
    int tid = threadIdx.x;
    int bs0 = blockIdx.x * 4;

    for (int bl = 0; bl < 4; bl++) {
        int b = bs0 + bl;
        if (tid == 0) {
            float M = -1e30f;
            for (int i = 0; i < NT; i++) M = fmaxf(M, d_mloc[b * NT + i]);
            float Z = 0.f;
            for (int i = 0; i < NT; i++) {
                float cc = __expf(d_mloc[b * NT + i] - M);
                coef[i] = cc;
                Z += cc * d_zloc[b * NT + i];
            }
            zinv_s = 1.0f / Z;
        }
        __syncthreads();
        if (tid < HH) {
            float s = 0.f;
            #pragma unroll
            for (int i = 0; i < NT; i++)
                s += coef[i] * d_ctxp[((long)b * NT + i) * HH + tid];
            ctx4[bl][tid] = s * zinv_s;
        }
        __syncthreads();
    }
    for (int i = tid; i < 4 * HH; i += 256)
        h04[i / HH][i % HH] = h0[(bs0 + i / HH) * HH + i % HH];
    __syncthreads();

    for (int g = tid; g < 800; g += 256) {
        float bias = b_ih[g] + b_hh[g];
        float a0 = bias, a1 = bias, a2 = bias, a3 = bias;
        const float* wh = W_hh + g * HH;
        #pragma unroll 4
        for (int k = 0; k < HH; k++) {
            float wv = wh[k];
            a0 += wv * h04[0][k]; a1 += wv * h04[1][k];
            a2 += wv * h04[2][k]; a3 += wv * h04[3][k];
        }
        const float* wi = W_ih + g * 201 + 1;
        #pragma unroll 4
        for (int k = 0; k < HH; k++) {
            float wv = wi[k];
            a0 += wv * ctx4[0][k]; a1 += wv * ctx4[1][k];
            a2 += wv * ctx4[2][k]; a3 += wv * ctx4[3][k];
        }
        gb4[0][g] = a0; gb4[1][g] = a1; gb4[2][g] = a2; gb4[3][g] = a3;
    }
    __syncthreads();

    for (int bl = 0; bl < 4; bl++) {
        int b = bs0 + bl;
        if (tid == 0) xb = x[b];
        __syncthreads();
        for (int step = 0; step < 5; step++) {
            if (tid < HH) {
                float xv = xb;
                float gi = gb4[bl][tid]       + W_ih[tid * 201]         * xv;
                float gf = gb4[bl][200 + tid] + W_ih[(200 + tid) * 201] * xv;
                float gg = gb4[bl][400 + tid] + W_ih[(400 + tid) * 201] * xv;
                float go = gb4[bl][600 + tid] + W_ih[(600 + tid) * 201] * xv;
                float cp = c0[b * HH + tid];
                float cn = sigf(gf) * cp + sigf(gi) * tanhf(gg);
                float hn = sigf(go) * tanhf(cn);
                r[tid] = fmaxf(hn, 0.0f);
            }
            __syncthreads();
            if (tid < 100) {
                float acc = b1[tid];
                const float* wr = W1 + tid * HH;
                #pragma unroll 4
                for (int k = 0; k < HH; k++) acc += wr[k] * r[k];
                s1[tid] = fmaxf(acc, 0.0f);
            }
            __syncthreads();
            if (tid < 50) {
                float acc = b2[tid];
                const float* wr = W2 + tid * 100;
                #pragma unroll 4
                for (int k = 0; k < 100; k++) acc += wr[k] * s1[k];
                s2[tid] = fmaxf(acc, 0.0f);
            }
            __syncthreads();
            if (tid == 0) {
                float acc = b3[0];
                #pragma unroll
                for (int k = 0; k < 50; k++) acc += W3[k] * s2[k];
                out[b * 5 + step] = acc;
                xb = acc;
            }
            __syncthreads();
        }
    }
}

// ---------------- launch ----------------
extern "C" void kernel_launch(void* const* d_in, const int* in_sizes, int n_in,
                              void* d_out, int out_size) {
    const float* x    = (const float*)d_in[0];
    const float* h0   = (const float*)d_in[1];
    const float* c0   = (const float*)d_in[2];
    const float* enc  = (const float*)d_in[3];
    const float* Wa   = (const float*)d_in[4];
    const float* ba   = (const float*)d_in[5];
    const float* Ua   = (const float*)d_in[6];
    const float* bua  = (const float*)d_in[7];
    const float* Va   = (const float*)d_in[8];
    const float* bva  = (const float*)d_in[9];
    const float* W_ih = (const float*)d_in[10];
    const float* W_hh = (const float*)d_in[11];
    const float* b_ih = (const float*)d_in[12];
    const float* b_hh = (const float*)d_in[13];
    const float* W1   = (const float*)d_in[14];
    const float* b1   = (const float*)d_in[15];
    const float* W2   = (const float*)d_in[16];
    const float* b2   = (const float*)d_in[17];
    const float* W3   = (const float*)d_in[18];
    const float* b3   = (const float*)d_in[19];
    float* out = (float*)d_out;
    (void)bva;

    cudaFuncSetAttribute(scores_kernel,
                         cudaFuncAttributeMaxDynamicSharedMemorySize, SMEM_SZ);

    setup_kernel<<<BB + 1, 256>>>(h0, Wa, ba, Ua, bua, Va);
    scores_kernel<<<dim3(NT, BB), 256, SMEM_SZ>>>(enc);
    decoder_kernel<<<BB / 4, 256>>>(x, h0, c0, W_ih, W_hh, b_ih, b_hh,
                                    W1, b1, W2, b2, W3, b3, out);
}